// round 12
// baseline (speedup 1.0000x reference)
#include <cuda_runtime.h>

// TT-linear: y = x @ W^T + bias
//   c0: [1,32(o0),32(i0),4(r1)]  c1: [4(r1),16(o1),16(i1),4(r2)]  c2: [4(r2),16(o2),16(i2),1]
//
// Kernel 0: out = bias (broadcast fill).
// Kernel 1: grid 512 = (token-pair 64) x (i0-half 2) x (o1-quarter 4); 128 thr;
//   __launch_bounds__(128,4) -> 4 INDEPENDENT CTAs/SM (desynchronized barriers).
//   Lane map: o2 = tid&15, z = (tid>>4)&1, o1p = tid>>5 (0..3, warp-uniform).
//   T=2 tokens per CTA; step1: each thread produces A rows i1 = (4z+o1p) and +8
//   for both tokens; step2: z splits i1-range, c1 near-broadcast, shfl_xor combine;
//   step3: z splits o0-range. ONE __syncthreads per slice.
//   Epilogue: RED.ADD into bias-prefilled out.

#define THREADS 128

typedef unsigned long long u64;

__device__ __forceinline__ u64 pk2(float lo, float hi) {
    u64 r;
    asm("mov.b64 %0, {%1, %2};" : "=l"(r) : "f"(lo), "f"(hi));
    return r;
}
__device__ __forceinline__ void unpk(u64 v, float& lo, float& hi) {
    asm("mov.b64 {%0, %1}, %2;" : "=f"(lo), "=f"(hi) : "l"(v));
}
__device__ __forceinline__ u64 fma2(u64 a, u64 b, u64 c) {
    u64 d;
    asm("fma.rn.f32x2 %0, %1, %2, %3;" : "=l"(d) : "l"(a), "l"(b), "l"(c));
    return d;
}
__device__ __forceinline__ float hadd(u64 v) {
    float lo, hi;
    unpk(v, lo, hi);
    return lo + hi;
}

// step1 for one A row (i1), both tokens, shared c2 loads.
__device__ __forceinline__ void step1_row(const float* __restrict__ Xs0,
                                          const float* __restrict__ Xs1,
                                          float* __restrict__ Ad0,
                                          float* __restrict__ Ad1,
                                          const float* __restrict__ sc2,
                                          int i1, int o2)
{
    u64 a01_0 = 0ull, a23_0 = 0ull, a01_1 = 0ull, a23_1 = 0ull;
    #pragma unroll
    for (int ch = 0; ch < 2; ch++) {
        const float4* xq0 = reinterpret_cast<const float4*>(&Xs0[i1 * 16 + ch * 8]);
        const float4* xq1 = reinterpret_cast<const float4*>(&Xs1[i1 * 16 + ch * 8]);
        float4 p0 = xq0[0], p1 = xq0[1];
        float4 q0 = xq1[0], q1 = xq1[1];
        float xs0[8] = { p0.x,p0.y,p0.z,p0.w, p1.x,p1.y,p1.z,p1.w };
        float xs1[8] = { q0.x,q0.y,q0.z,q0.w, q1.x,q1.y,q1.z,q1.w };
        #pragma unroll
        for (int j = 0; j < 8; j++) {
            const int i2 = ch * 8 + j;
            ulonglong2 c = *reinterpret_cast<const ulonglong2*>(&sc2[(i2 * 16 + o2) * 4]);
            u64 xd0 = pk2(xs0[j], xs0[j]);
            u64 xd1 = pk2(xs1[j], xs1[j]);
            a01_0 = fma2(xd0, c.x, a01_0);
            a23_0 = fma2(xd0, c.y, a23_0);
            a01_1 = fma2(xd1, c.x, a01_1);
            a23_1 = fma2(xd1, c.y, a23_1);
        }
    }
    ulonglong2 st0; st0.x = a01_0; st0.y = a23_0;
    ulonglong2 st1; st1.x = a01_1; st1.y = a23_1;
    *reinterpret_cast<ulonglong2*>(&Ad0[(i1 * 16 + o2) * 4]) = st0;
    *reinterpret_cast<ulonglong2*>(&Ad1[(i1 * 16 + o2) * 4]) = st1;
}

__global__ __launch_bounds__(THREADS, 4)
void tt_partial_kernel(const float* __restrict__ x,
                       const float* __restrict__ g0,
                       const float* __restrict__ g1,
                       const float* __restrict__ g2,
                       float* __restrict__ out)
{
    __shared__ __align__(16) float sc0[2048];       // [it 16][r1 4][o0 32]
    __shared__ __align__(16) float sc1[1024];       // [o1p 4][i1 16][r1 4][r2 4]
    __shared__ __align__(16) float sc2[1024];       // [i2][o2][r2]
    __shared__ __align__(16) float sA[2][2][1024];  // [buf][tok][i1][o2][r2]
    __shared__ __align__(16) float sX[2][2][256];   // [buf][tok][elem]

    const int tid    = threadIdx.x;
    const int o2     = tid & 15;
    const int z      = (tid >> 4) & 1;
    const int o1p    = tid >> 5;                    // 0..3; warp-uniform
    const int pair   = blockIdx.x & 63;
    const int half   = (blockIdx.x >> 6) & 1;
    const int o1q    = blockIdx.x >> 7;             // 0..3
    const int i0base = half * 16;

    // ---- core relayout into smem (stride 128) ----
    for (int idx = tid; idx < 2048; idx += THREADS) {
        int o0 = idx & 31, r1 = (idx >> 5) & 3, it = idx >> 7;
        sc0[idx] = g0[(o0 * 32 + i0base + it) * 4 + r1];
    }
    for (int idx = tid; idx < 1024; idx += THREADS) {
        int r2 = idx & 3, r1 = (idx >> 2) & 3, i1 = (idx >> 4) & 15, og = idx >> 8;  // 0..3
        sc1[idx] = g1[((r1 * 16 + o1q * 4 + og) * 16 + i1) * 4 + r2];
    }
    for (int idx = tid; idx < 1024; idx += THREADS) {
        int r2 = idx & 3, o2g = (idx >> 2) & 15, i2 = idx >> 6;
        sc2[idx] = g2[(r2 * 16 + o2g) * 16 + i2];
    }

    const float* x0 = x + (2 * pair + 0) * 8192;
    const float* x1 = x + (2 * pair + 1) * 8192;

    // stage slices 0 and 1 for both tokens (2 floats per thread per (buf,tok))
    sX[0][0][tid]       = x0[(i0base + 0) * 256 + tid];
    sX[0][0][tid + 128] = x0[(i0base + 0) * 256 + 128 + tid];
    sX[0][1][tid]       = x1[(i0base + 0) * 256 + tid];
    sX[0][1][tid + 128] = x1[(i0base + 0) * 256 + 128 + tid];
    sX[1][0][tid]       = x0[(i0base + 1) * 256 + tid];
    sX[1][0][tid + 128] = x0[(i0base + 1) * 256 + 128 + tid];
    sX[1][1][tid]       = x1[(i0base + 1) * 256 + tid];
    sX[1][1][tid + 128] = x1[(i0base + 1) * 256 + 128 + tid];

    u64 yp0[8], yp1[8];                   // per-token y, own z o0-half (16 o0 = 8 pairs)
    #pragma unroll
    for (int i = 0; i < 8; i++) { yp0[i] = 0ull; yp1[i] = 0ull; }

    const int i1a = 4 * z + o1p;          // this thread's two produced A rows
    const int i1b = 8 + 4 * z + o1p;

    __syncthreads();

    // prologue: step1 for slice 0 (both rows, both tokens) into sA[0]
    step1_row(sX[0][0], sX[0][1], sA[0][0], sA[0][1], sc2, i1a, o2);
    step1_row(sX[0][0], sX[0][1], sA[0][0], sA[0][1], sc2, i1b, o2);
    float xn00 = x0[(i0base + 2) * 256 + tid];
    float xn01 = x0[(i0base + 2) * 256 + 128 + tid];
    float xn10 = x1[(i0base + 2) * 256 + tid];
    float xn11 = x1[(i0base + 2) * 256 + 128 + tid];
    __syncthreads();

    for (int k = 0; k < 16; k++) {
        const int b = k & 1;

        // ---- step 2: partial B over own i1-half, both tokens ----
        u64 a0[4][2], a1[4][2];
        #pragma unroll
        for (int r1 = 0; r1 < 4; r1++) {
            a0[r1][0] = 0ull; a0[r1][1] = 0ull;
            a1[r1][0] = 0ull; a1[r1][1] = 0ull;
        }
        #pragma unroll
        for (int s = 0; s < 8; s++) {
            const int i1 = z * 8 + s;
            const ulonglong2 av0 = *reinterpret_cast<const ulonglong2*>(
                &sA[b][0][(i1 * 16 + o2) * 4]);
            const ulonglong2 av1 = *reinterpret_cast<const ulonglong2*>(
                &sA[b][1][(i1 * 16 + o2) * 4]);
            const ulonglong2* cp = reinterpret_cast<const ulonglong2*>(
                &sc1[o1p * 256 + i1 * 16]);            // near-broadcast (2 addrs/warp)
            #pragma unroll
            for (int r1 = 0; r1 < 4; r1++) {
                ulonglong2 c = cp[r1];
                a0[r1][0] = fma2(av0.x, c.x, a0[r1][0]);
                a0[r1][1] = fma2(av0.y, c.y, a0[r1][1]);
                a1[r1][0] = fma2(av1.x, c.x, a1[r1][0]);
                a1[r1][1] = fma2(av1.y, c.y, a1[r1][1]);
            }
        }
        // combine z-halves via shfl_xor (partner = lane^16), build duplicated B
        u64 bd0[4], bd1[4];
        #pragma unroll
        for (int r1 = 0; r1 < 4; r1++) {
            float p0 = hadd(a0[r1][0]) + hadd(a0[r1][1]);
            float p1 = hadd(a1[r1][0]) + hadd(a1[r1][1]);
            p0 += __shfl_xor_sync(0xffffffffu, p0, 16);
            p1 += __shfl_xor_sync(0xffffffffu, p1, 16);
            bd0[r1] = pk2(p0, p0);
            bd1[r1] = pk2(p1, p1);
        }

        // ---- step 3: own z o0-half, both tokens; c0 loads shared ----
        #pragma unroll
        for (int r1 = 0; r1 < 4; r1++) {
            const ulonglong2* cq = reinterpret_cast<const ulonglong2*>(
                &sc0[k * 128 + r1 * 32 + z * 16]);
            #pragma unroll
            for (int q = 0; q < 4; q++) {
                ulonglong2 c = cq[q];                  // o0' = 4q..4q+3 within half
                yp0[2 * q]     = fma2(bd0[r1], c.x, yp0[2 * q]);
                yp0[2 * q + 1] = fma2(bd0[r1], c.y, yp0[2 * q + 1]);
                yp1[2 * q]     = fma2(bd1[r1], c.x, yp1[2 * q]);
                yp1[2 * q + 1] = fma2(bd1[r1], c.y, yp1[2 * q + 1]);
            }
        }

        // ---- step 1 for slice k+1 (both rows); stage slice k+2; one sync ----
        if (k < 15) {
            const int nb = (k + 1) & 1;
            step1_row(sX[nb][0], sX[nb][1], sA[nb][0], sA[nb][1], sc2, i1a, o2);
            step1_row(sX[nb][0], sX[nb][1], sA[nb][0], sA[nb][1], sc2, i1b, o2);
            if (k < 14) {
                sX[b][0][tid]       = xn00;
                sX[b][0][tid + 128] = xn01;
                sX[b][1][tid]       = xn10;
                sX[b][1][tid + 128] = xn11;
                if (k < 13) {
                    xn00 = x0[(i0base + k + 3) * 256 + tid];
                    xn01 = x0[(i0base + k + 3) * 256 + 128 + tid];
                    xn10 = x1[(i0base + k + 3) * 256 + tid];
                    xn11 = x1[(i0base + k + 3) * 256 + 128 + tid];
                }
            }
            __syncthreads();
        }
    }

    // ---- epilogue: RED.ADD into bias-prefilled out ----
    const int col = (o1q * 4 + o1p) * 16 + o2;
    float* ob0 = out + (size_t)(2 * pair + 0) * 8192 + (z * 16) * 256 + col;
    float* ob1 = out + (size_t)(2 * pair + 1) * 8192 + (z * 16) * 256 + col;
    #pragma unroll
    for (int q = 0; q < 4; q++) {
        float f0, f1, f2, f3, h0, h1, h2, h3;
        unpk(yp0[2 * q],     f0, f1);
        unpk(yp0[2 * q + 1], f2, f3);
        unpk(yp1[2 * q],     h0, h1);
        unpk(yp1[2 * q + 1], h2, h3);
        atomicAdd(ob0 + (4 * q + 0) * 256, f0);
        atomicAdd(ob0 + (4 * q + 1) * 256, f1);
        atomicAdd(ob0 + (4 * q + 2) * 256, f2);
        atomicAdd(ob0 + (4 * q + 3) * 256, f3);
        atomicAdd(ob1 + (4 * q + 0) * 256, h0);
        atomicAdd(ob1 + (4 * q + 1) * 256, h1);
        atomicAdd(ob1 + (4 * q + 2) * 256, h2);
        atomicAdd(ob1 + (4 * q + 3) * 256, h3);
    }
}

__global__ __launch_bounds__(128)
void tt_bias_kernel(const float* __restrict__ bias, float* __restrict__ out)
{
    // out = 262144 float4 = 128 copies of bias (2048 float4 each); grid 2048
    const int v = blockIdx.x * 128 + threadIdx.x;
    reinterpret_cast<float4*>(out)[v] =
        reinterpret_cast<const float4*>(bias)[v & 2047];
}

extern "C" void kernel_launch(void* const* d_in, const int* in_sizes, int n_in,
                              void* d_out, int out_size)
{
    const float* x    = (const float*)d_in[0];  // [128, 8192]
    const float* g0   = (const float*)d_in[1];  // [1,32,32,4]
    const float* g1   = (const float*)d_in[2];  // [4,16,16,4]
    const float* g2   = (const float*)d_in[3];  // [4,16,16,1]
    const float* bias = (const float*)d_in[4];  // [8192]
    float* out = (float*)d_out;                 // [128, 8192]

    tt_bias_kernel<<<2048, 128>>>(bias, out);
    tt_partial_kernel<<<512, THREADS>>>(x, g0, g1, g2, out);
}

// round 13
// speedup vs baseline: 2.0958x; 2.0958x over previous
#include <cuda_runtime.h>

// TT-linear: y = x @ W^T + bias
//   c0: [1,32(o0),32(i0),4(r1)]  c1: [4(r1),16(o1),16(i1),4(r2)]  c2: [4(r2),16(o2),16(i2),1]
//
// Kernel 0: out = bias (broadcast fill).
// Kernel 1: grid 256 = (token-pair 64) x (i0-quarter 4); 256 thr; 2 CTAs/SM; ONE wave.
//   Lane map: o2 = tid&15, z = (tid>>4)&1, o1p = tid>>5 (0..7, warp-uniform).
//   CTA covers ALL o1 -> zero step-1 duplication (chip-total fma2 = minimum 234M).
//   Each thread computes B for TWO o1 (o1p, o1p+8): A-read bytes per fma2 halved.
//   step1: thread produces A row i1=2*o1p+z, both tokens, shared c2 loads.
//   step2: z splits i1 (8 each); 16 single-u64 acc chains; shfl_xor(16) combine.
//   step3: z splits o0; c0 loads shared across tokens AND both o1.
//   ONE __syncthreads per slice. Epilogue: RED.ADD into bias-prefilled out (4 CTAs/elem).

#define THREADS 256

typedef unsigned long long u64;

__device__ __forceinline__ u64 pk2(float lo, float hi) {
    u64 r;
    asm("mov.b64 %0, {%1, %2};" : "=l"(r) : "f"(lo), "f"(hi));
    return r;
}
__device__ __forceinline__ void unpk(u64 v, float& lo, float& hi) {
    asm("mov.b64 {%0, %1}, %2;" : "=f"(lo), "=f"(hi) : "l"(v));
}
__device__ __forceinline__ u64 fma2(u64 a, u64 b, u64 c) {
    u64 d;
    asm("fma.rn.f32x2 %0, %1, %2, %3;" : "=l"(d) : "l"(a), "l"(b), "l"(c));
    return d;
}
__device__ __forceinline__ float hadd(u64 v) {
    float lo, hi;
    unpk(v, lo, hi);
    return lo + hi;
}

// step1: A_t[i1][o2][r2] for BOTH tokens, one i1 row, shared c2 loads.
__device__ __forceinline__ void step1_both(const float* __restrict__ Xs0,
                                           const float* __restrict__ Xs1,
                                           float* __restrict__ Ad0,
                                           float* __restrict__ Ad1,
                                           const float* __restrict__ sc2,
                                           int i1, int o2)
{
    u64 a01_0 = 0ull, a23_0 = 0ull, a01_1 = 0ull, a23_1 = 0ull;
    #pragma unroll
    for (int ch = 0; ch < 2; ch++) {
        const float4* xq0 = reinterpret_cast<const float4*>(&Xs0[i1 * 16 + ch * 8]);
        const float4* xq1 = reinterpret_cast<const float4*>(&Xs1[i1 * 16 + ch * 8]);
        float4 p0 = xq0[0], p1 = xq0[1];
        float4 q0 = xq1[0], q1 = xq1[1];
        float xs0[8] = { p0.x,p0.y,p0.z,p0.w, p1.x,p1.y,p1.z,p1.w };
        float xs1[8] = { q0.x,q0.y,q0.z,q0.w, q1.x,q1.y,q1.z,q1.w };
        #pragma unroll
        for (int j = 0; j < 8; j++) {
            const int i2 = ch * 8 + j;
            ulonglong2 c = *reinterpret_cast<const ulonglong2*>(&sc2[(i2 * 16 + o2) * 4]);
            u64 xd0 = pk2(xs0[j], xs0[j]);
            u64 xd1 = pk2(xs1[j], xs1[j]);
            a01_0 = fma2(xd0, c.x, a01_0);
            a23_0 = fma2(xd0, c.y, a23_0);
            a01_1 = fma2(xd1, c.x, a01_1);
            a23_1 = fma2(xd1, c.y, a23_1);
        }
    }
    ulonglong2 st0; st0.x = a01_0; st0.y = a23_0;
    ulonglong2 st1; st1.x = a01_1; st1.y = a23_1;
    *reinterpret_cast<ulonglong2*>(&Ad0[(i1 * 16 + o2) * 4]) = st0;
    *reinterpret_cast<ulonglong2*>(&Ad1[(i1 * 16 + o2) * 4]) = st1;
}

__global__ __launch_bounds__(THREADS, 2)
void tt_partial_kernel(const float* __restrict__ x,
                       const float* __restrict__ g0,
                       const float* __restrict__ g1,
                       const float* __restrict__ g2,
                       float* __restrict__ out)
{
    __shared__ __align__(16) float sc0[1024];       // [it 8][r1 4][o0 32]
    __shared__ __align__(16) float sc1[4096];       // [o1 16][i1 16][r1 4][r2 4]
    __shared__ __align__(16) float sc2[1024];       // [i2][o2][r2]
    __shared__ __align__(16) float sA[2][2][1024];  // [buf][tok][i1][o2][r2]
    __shared__ __align__(16) float sX[2][2][256];   // [buf][tok][elem]

    const int tid     = threadIdx.x;
    const int o2      = tid & 15;
    const int z       = (tid >> 4) & 1;
    const int o1p     = tid >> 5;                   // 0..7; warp-uniform
    const int pair    = blockIdx.x & 63;
    const int quarter = blockIdx.x >> 6;            // 0..3
    const int i0base  = quarter * 8;                // 8 slices per CTA

    // ---- core relayout into smem ----
    for (int idx = tid; idx < 1024; idx += THREADS) {
        int o0 = idx & 31, r1 = (idx >> 5) & 3, it = idx >> 7;      // it = 0..7
        sc0[idx] = g0[(o0 * 32 + i0base + it) * 4 + r1];
    }
    for (int idx = tid; idx < 4096; idx += THREADS) {
        int r2 = idx & 3, r1 = (idx >> 2) & 3, i1 = (idx >> 4) & 15, o1 = idx >> 8;
        sc1[idx] = g1[((r1 * 16 + o1) * 16 + i1) * 4 + r2];
    }
    for (int idx = tid; idx < 1024; idx += THREADS) {
        int r2 = idx & 3, o2g = (idx >> 2) & 15, i2 = idx >> 6;
        sc2[idx] = g2[(r2 * 16 + o2g) * 16 + i2];
    }

    const float* x0 = x + (2 * pair + 0) * 8192;
    const float* x1 = x + (2 * pair + 1) * 8192;

    sX[0][0][tid] = x0[(i0base + 0) * 256 + tid];
    sX[0][1][tid] = x1[(i0base + 0) * 256 + tid];
    sX[1][0][tid] = x0[(i0base + 1) * 256 + tid];
    sX[1][1][tid] = x1[(i0base + 1) * 256 + tid];

    u64 yp[2][2][8];                      // [o1sel][tok][o0'-pair], own z o0-half
    #pragma unroll
    for (int a = 0; a < 2; a++)
        #pragma unroll
        for (int t = 0; t < 2; t++)
            #pragma unroll
            for (int i = 0; i < 8; i++) yp[a][t][i] = 0ull;

    const int i1prod = 2 * o1p + z;

    __syncthreads();

    step1_both(sX[0][0], sX[0][1], sA[0][0], sA[0][1], sc2, i1prod, o2);
    float xn0 = x0[(i0base + 2) * 256 + tid];
    float xn1 = x1[(i0base + 2) * 256 + tid];
    __syncthreads();

    for (int k = 0; k < 8; k++) {
        const int b = k & 1;

        // ---- step 2: B over own i1-half, BOTH o1, both tokens (16 acc chains) ----
        u64 acc[2][2][4];                 // [o1sel][tok][r1]
        #pragma unroll
        for (int a = 0; a < 2; a++)
            #pragma unroll
            for (int t = 0; t < 2; t++)
                #pragma unroll
                for (int r1 = 0; r1 < 4; r1++) acc[a][t][r1] = 0ull;

        const float* A0 = sA[b][0];
        const float* A1 = sA[b][1];
        #pragma unroll
        for (int s = 0; s < 8; s++) {
            const int i1 = z * 8 + s;
            const ulonglong2 av0 = *reinterpret_cast<const ulonglong2*>(
                &A0[(i1 * 16 + o2) * 4]);
            const ulonglong2 av1 = *reinterpret_cast<const ulonglong2*>(
                &A1[(i1 * 16 + o2) * 4]);
            const ulonglong2* cpA = reinterpret_cast<const ulonglong2*>(
                &sc1[(o1p * 16 + i1) * 16]);
            const ulonglong2* cpB = reinterpret_cast<const ulonglong2*>(
                &sc1[((o1p + 8) * 16 + i1) * 16]);
            #pragma unroll
            for (int r1 = 0; r1 < 4; r1++) {
                ulonglong2 cA = cpA[r1];
                ulonglong2 cB = cpB[r1];
                acc[0][0][r1] = fma2(av0.x, cA.x, acc[0][0][r1]);
                acc[0][0][r1] = fma2(av0.y, cA.y, acc[0][0][r1]);
                acc[0][1][r1] = fma2(av1.x, cA.x, acc[0][1][r1]);
                acc[0][1][r1] = fma2(av1.y, cA.y, acc[0][1][r1]);
                acc[1][0][r1] = fma2(av0.x, cB.x, acc[1][0][r1]);
                acc[1][0][r1] = fma2(av0.y, cB.y, acc[1][0][r1]);
                acc[1][1][r1] = fma2(av1.x, cB.x, acc[1][1][r1]);
                acc[1][1][r1] = fma2(av1.y, cB.y, acc[1][1][r1]);
            }
        }
        // combine z-halves (partner lane^16) -> duplicated B scalars
        u64 bd[2][2][4];
        #pragma unroll
        for (int a = 0; a < 2; a++)
            #pragma unroll
            for (int t = 0; t < 2; t++)
                #pragma unroll
                for (int r1 = 0; r1 < 4; r1++) {
                    float p = hadd(acc[a][t][r1]);
                    p += __shfl_xor_sync(0xffffffffu, p, 16);
                    bd[a][t][r1] = pk2(p, p);
                }

        // ---- step 3: own z o0-half; c0 loads shared across tok and both o1 ----
        #pragma unroll
        for (int r1 = 0; r1 < 4; r1++) {
            const ulonglong2* cq = reinterpret_cast<const ulonglong2*>(
                &sc0[k * 128 + r1 * 32 + z * 16]);
            #pragma unroll
            for (int q = 0; q < 4; q++) {
                ulonglong2 c = cq[q];                  // o0' = 4q..4q+3 within half
                yp[0][0][2 * q]     = fma2(bd[0][0][r1], c.x, yp[0][0][2 * q]);
                yp[0][0][2 * q + 1] = fma2(bd[0][0][r1], c.y, yp[0][0][2 * q + 1]);
                yp[0][1][2 * q]     = fma2(bd[0][1][r1], c.x, yp[0][1][2 * q]);
                yp[0][1][2 * q + 1] = fma2(bd[0][1][r1], c.y, yp[0][1][2 * q + 1]);
                yp[1][0][2 * q]     = fma2(bd[1][0][r1], c.x, yp[1][0][2 * q]);
                yp[1][0][2 * q + 1] = fma2(bd[1][0][r1], c.y, yp[1][0][2 * q + 1]);
                yp[1][1][2 * q]     = fma2(bd[1][1][r1], c.x, yp[1][1][2 * q]);
                yp[1][1][2 * q + 1] = fma2(bd[1][1][r1], c.y, yp[1][1][2 * q + 1]);
            }
        }

        // ---- step 1 for slice k+1; stage slice k+2; one sync ----
        if (k < 7) {
            const int nb = (k + 1) & 1;
            step1_both(sX[nb][0], sX[nb][1], sA[nb][0], sA[nb][1], sc2, i1prod, o2);
            if (k < 6) {
                sX[b][0][tid] = xn0;
                sX[b][1][tid] = xn1;
                if (k < 5) {
                    xn0 = x0[(i0base + k + 3) * 256 + tid];
                    xn1 = x1[(i0base + k + 3) * 256 + tid];
                }
            }
            __syncthreads();
        }
    }

    // ---- epilogue: RED.ADD into bias-prefilled out ----
    #pragma unroll
    for (int a = 0; a < 2; a++) {
        const int col = (o1p + 8 * a) * 16 + o2;
        #pragma unroll
        for (int t = 0; t < 2; t++) {
            float* ob = out + (size_t)(2 * pair + t) * 8192 + (z * 16) * 256 + col;
            #pragma unroll
            for (int q = 0; q < 4; q++) {
                float f0, f1, f2, f3;
                unpk(yp[a][t][2 * q],     f0, f1);
                unpk(yp[a][t][2 * q + 1], f2, f3);
                atomicAdd(ob + (4 * q + 0) * 256, f0);
                atomicAdd(ob + (4 * q + 1) * 256, f1);
                atomicAdd(ob + (4 * q + 2) * 256, f2);
                atomicAdd(ob + (4 * q + 3) * 256, f3);
            }
        }
    }
}

__global__ __launch_bounds__(128)
void tt_bias_kernel(const float* __restrict__ bias, float* __restrict__ out)
{
    // out = 262144 float4 = 128 copies of bias (2048 float4 each); grid 2048
    const int v = blockIdx.x * 128 + threadIdx.x;
    reinterpret_cast<float4*>(out)[v] =
        reinterpret_cast<const float4*>(bias)[v & 2047];
}

extern "C" void kernel_launch(void* const* d_in, const int* in_sizes, int n_in,
                              void* d_out, int out_size)
{
    const float* x    = (const float*)d_in[0];  // [128, 8192]
    const float* g0   = (const float*)d_in[1];  // [1,32,32,4]
    const float* g1   = (const float*)d_in[2];  // [4,16,16,4]
    const float* g2   = (const float*)d_in[3];  // [4,16,16,1]
    const float* bias = (const float*)d_in[4];  // [8192]
    float* out = (float*)d_out;                 // [128, 8192]

    tt_bias_kernel<<<2048, 128>>>(bias, out);
    tt_partial_kernel<<<256, THREADS>>>(x, g0, g1, g2, out);
}